// round 1
// baseline (speedup 1.0000x reference)
#include <cuda_runtime.h>

// Problem constants
#define BB 4
#define HH 16
#define SS 2048
#define DKK 64
#define DVV 64

#define SBLK 16      // q rows per block
#define KTILE 128    // keys per smem tile
#define NTHREADS 256
#define KV_STRIDE 68 // padded row stride (floats) for K/V tile: conflict-free LDS.128

// dynamic smem layout (floats):
//   p_s  [SBLK][SS]          = 32768 floats (scores -> probs)
//   q_s  [SBLK][DKK]         = 1024 floats (pre-scaled by 1/temperature)
//   kv_s [KTILE][KV_STRIDE]  = 8704 floats (K tile, then reused as V tile)
#define SMEM_FLOATS (SBLK * SS + SBLK * DKK + KTILE * KV_STRIDE)

__global__ __launch_bounds__(NTHREADS, 1)
void psdpa_kernel(const float* __restrict__ q,
                  const float* __restrict__ k,
                  const float* __restrict__ v,
                  const int* __restrict__ mask,
                  float* __restrict__ out,
                  float* __restrict__ attn)
{
    extern __shared__ float smem[];
    float* p_s  = smem;                       // [SBLK][SS]
    float* q_s  = smem + SBLK * SS;           // [SBLK][DKK]
    float* kv_s = q_s + SBLK * DKK;           // [KTILE][KV_STRIDE]

    const int tid  = threadIdx.x;
    const int w    = tid >> 5;
    const int lane = tid & 31;

    const int bh = blockIdx.y;          // 0..63
    const int b  = bh >> 4;             // mask broadcast over heads
    const int q0 = blockIdx.x * SBLK;   // first q row of this block

    const float* qbase = q + (size_t)bh * SS * DKK + (size_t)q0 * DKK;
    const float* kbase = k + (size_t)bh * SS * DKK;
    const float* vbase = v + (size_t)bh * SS * DVV;

    // ---- load Q block (scaled by 1/temperature = 0.125) ----
    {
        const float4* qg = (const float4*)qbase;   // 1024 floats = 256 float4
        float4 t = qg[tid];
        t.x *= 0.125f; t.y *= 0.125f; t.z *= 0.125f; t.w *= 0.125f;
        ((float4*)q_s)[tid] = t;
    }

    const int r0 = 2 * w;
    const int r1 = 2 * w + 1;

    // =========================== QK^T ===========================
    for (int kt = 0; kt < SS / KTILE; ++kt) {
        __syncthreads();
        // load K tile [KTILE][DKK] -> kv_s with row stride KV_STRIDE
        {
            const float4* kg = (const float4*)(kbase + (size_t)kt * KTILE * DKK);
            #pragma unroll
            for (int i = 0; i < (KTILE * DKK / 4) / NTHREADS; ++i) { // 8 iters
                int idx = tid + i * NTHREADS;
                int j  = idx >> 4;          // key row
                int d4 = (idx & 15) << 2;   // d offset
                float4 t = kg[idx];
                *(float4*)(kv_s + j * KV_STRIDE + d4) = t;
            }
        }
        __syncthreads();

        // each warp: 2 rows x 128 keys (lane covers 4 keys, one per kk group)
        float s00 = 0.f, s01 = 0.f, s02 = 0.f, s03 = 0.f;
        float s10 = 0.f, s11 = 0.f, s12 = 0.f, s13 = 0.f;
        const float* k0 = kv_s + (0 * 32 + lane) * KV_STRIDE;
        const float* k1 = kv_s + (1 * 32 + lane) * KV_STRIDE;
        const float* k2 = kv_s + (2 * 32 + lane) * KV_STRIDE;
        const float* k3 = kv_s + (3 * 32 + lane) * KV_STRIDE;
        const float* qr0 = q_s + r0 * DKK;
        const float* qr1 = q_s + r1 * DKK;

        #pragma unroll
        for (int d = 0; d < DKK; d += 4) {
            float4 a0 = *(const float4*)(qr0 + d);   // broadcast
            float4 a1 = *(const float4*)(qr1 + d);   // broadcast
            float4 c0 = *(const float4*)(k0 + d);
            float4 c1 = *(const float4*)(k1 + d);
            float4 c2 = *(const float4*)(k2 + d);
            float4 c3 = *(const float4*)(k3 + d);
            s00 += a0.x*c0.x + a0.y*c0.y + a0.z*c0.z + a0.w*c0.w;
            s01 += a0.x*c1.x + a0.y*c1.y + a0.z*c1.z + a0.w*c1.w;
            s02 += a0.x*c2.x + a0.y*c2.y + a0.z*c2.z + a0.w*c2.w;
            s03 += a0.x*c3.x + a0.y*c3.y + a0.z*c3.z + a0.w*c3.w;
            s10 += a1.x*c0.x + a1.y*c0.y + a1.z*c0.z + a1.w*c0.w;
            s11 += a1.x*c1.x + a1.y*c1.y + a1.z*c1.z + a1.w*c1.w;
            s12 += a1.x*c2.x + a1.y*c2.y + a1.z*c2.z + a1.w*c2.w;
            s13 += a1.x*c3.x + a1.y*c3.y + a1.z*c3.z + a1.w*c3.w;
        }
        int base = kt * KTILE + lane;
        p_s[r0 * SS + base +  0] = s00;
        p_s[r0 * SS + base + 32] = s01;
        p_s[r0 * SS + base + 64] = s02;
        p_s[r0 * SS + base + 96] = s03;
        p_s[r1 * SS + base +  0] = s10;
        p_s[r1 * SS + base + 32] = s11;
        p_s[r1 * SS + base + 64] = s12;
        p_s[r1 * SS + base + 96] = s13;
    }
    __syncthreads();

    // ====================== mask + softmax + attn store ======================
    // each warp handles its own 2 rows (it wrote them; no cross-warp dep)
    #pragma unroll
    for (int rr = 0; rr < 2; ++rr) {
        int r    = 2 * w + rr;
        int qrow = q0 + r;
        const int* mrow = mask + (size_t)b * SS * SS + (size_t)qrow * SS;
        float* prow = p_s + r * SS;
        float* arow = attn + (size_t)bh * SS * SS + (size_t)qrow * SS;

        // pass 1: apply mask, find max
        float vmax = -3.4e38f;
        for (int jj = lane; jj < SS; jj += 32) {
            float s = prow[jj];
            s = (mrow[jj] != 0) ? s : -1.0e9f;
            prow[jj] = s;
            vmax = fmaxf(vmax, s);
        }
        #pragma unroll
        for (int o = 16; o > 0; o >>= 1)
            vmax = fmaxf(vmax, __shfl_xor_sync(0xffffffffu, vmax, o));

        // pass 2: exp + sum
        float sum = 0.f;
        for (int jj = lane; jj < SS; jj += 32) {
            float e = __expf(prow[jj] - vmax);
            prow[jj] = e;
            sum += e;
        }
        #pragma unroll
        for (int o = 16; o > 0; o >>= 1)
            sum += __shfl_xor_sync(0xffffffffu, sum, o);
        float inv = 1.0f / sum;

        // pass 3: normalize, store to smem (for PV) and gmem (attn output)
        for (int jj = lane; jj < SS; jj += 32) {
            float pv = prow[jj] * inv;
            prow[jj] = pv;
            arow[jj] = pv;
        }
    }

    // =========================== P @ V ===========================
    float a00 = 0.f, a01 = 0.f, a10 = 0.f, a11 = 0.f; // [2 rows][2 dims]
    for (int vt = 0; vt < SS / KTILE; ++vt) {
        __syncthreads();
        {
            const float4* vg = (const float4*)(vbase + (size_t)vt * KTILE * DVV);
            #pragma unroll
            for (int i = 0; i < (KTILE * DVV / 4) / NTHREADS; ++i) { // 8 iters
                int idx = tid + i * NTHREADS;
                int j  = idx >> 4;
                int d4 = (idx & 15) << 2;
                float4 t = vg[idx];
                *(float4*)(kv_s + j * KV_STRIDE + d4) = t;
            }
        }
        __syncthreads();

        const float* p0 = p_s + r0 * SS + vt * KTILE;
        const float* p1 = p_s + r1 * SS + vt * KTILE;
        #pragma unroll 8
        for (int j = 0; j < KTILE; j += 2) {
            float2 pa = *(const float2*)(p0 + j);   // broadcast
            float2 pb = *(const float2*)(p1 + j);   // broadcast
            float2 v0 = *(const float2*)(kv_s + (j    ) * KV_STRIDE + 2 * lane);
            float2 v1 = *(const float2*)(kv_s + (j + 1) * KV_STRIDE + 2 * lane);
            a00 += pa.x * v0.x + pa.y * v1.x;
            a01 += pa.x * v0.y + pa.y * v1.y;
            a10 += pb.x * v0.x + pb.y * v1.x;
            a11 += pb.x * v0.y + pb.y * v1.y;
        }
    }

    // write output [2 rows][2 dims per lane]
    float* obase = out + (size_t)bh * SS * DVV + (size_t)q0 * DVV;
    *(float2*)(obase + r0 * DVV + 2 * lane) = make_float2(a00, a01);
    *(float2*)(obase + r1 * DVV + 2 * lane) = make_float2(a10, a11);
}

extern "C" void kernel_launch(void* const* d_in, const int* in_sizes, int n_in,
                              void* d_out, int out_size)
{
    const float* q    = (const float*)d_in[0];
    const float* k    = (const float*)d_in[1];
    const float* v    = (const float*)d_in[2];
    const int*   mask = (const int*)d_in[3];

    float* out  = (float*)d_out;                                   // [B,H,S,DV]
    float* attn = out + (size_t)BB * HH * SS * DVV;                // [B,H,S,S]

    static bool configured = false;
    if (!configured) {
        cudaFuncSetAttribute(psdpa_kernel,
                             cudaFuncAttributeMaxDynamicSharedMemorySize,
                             SMEM_FLOATS * sizeof(float));
        configured = true;
    }

    dim3 grid(SS / SBLK, BB * HH);
    psdpa_kernel<<<grid, NTHREADS, SMEM_FLOATS * sizeof(float)>>>(
        q, k, v, mask, out, attn);
}